// round 6
// baseline (speedup 1.0000x reference)
#include <cuda_runtime.h>
#include <math.h>

#define NPTS   524288
#define NLVL   16
#define TSIZE  (1 << 19)

// shared-memory parameter layout (floats) for the MLP kernel
#define OFF_W1 0        // [32,64]  2048
#define OFF_B1 2048     // [64]
#define OFF_W2 2112     // [64,16]  1024
#define OFF_B2 3136     // [16]
#define OFF_W3 3152     // [41,64]  2624
#define OFF_B3 5776     // [64]
#define OFF_W4 5840     // [64,64]  4096
#define OFF_B4 9936     // [64]
#define OFF_W5 10000    // [64,3]   192
#define OFF_B5 10192    // [3]
#define SMEM_TOTAL 10196

// packed f32x2 helpers (FFMA2 is only reachable via PTX on sm_103a)
#define FMA2(d, a, b, c) \
    asm("fma.rn.f32x2 %0, %1, %2, %3;" : "=l"(d) : "l"(a), "l"(b), "l"(c))
#define PACK2(d, lo, hi) \
    asm("mov.b64 %0, {%1, %2};" : "=l"(d) : "f"(lo), "f"(hi))
#define UNPACK2(lo, hi, v) \
    asm("mov.b64 {%0, %1}, %2;" : "=f"(lo), "=f"(hi) : "l"(v))

typedef unsigned long long u64;

// feature scratch, chunk-major: g_feat[c * NPTS + n] holds feat[4c..4c+3] of point n
__device__ float4 g_feat[8 * NPTS];

// ======================= Kernel A: hash-grid encode =======================
__global__ __launch_bounds__(256, 3) void encode_kernel(
    const float* __restrict__ pos,
    const float* __restrict__ tables)
{
    const int i = blockIdx.x * 256 + threadIdx.x;

    const float px = pos[3 * i + 0];
    const float py = pos[3 * i + 1];
    const float pz = pos[3 * i + 2];

    float feat[32];
#pragma unroll
    for (int l = 0; l < NLVL; l++) {
        const float res = (float)(16 << l);      // exact: growth factor b == 2.0
        const float fx = px * res, fy = py * res, fz = pz * res;
        const float bx = floorf(fx), by = floorf(fy), bz = floorf(fz);
        const int ix = (int)bx, iy = (int)by, iz = (int)bz;
        const float wx = fx - bx, wy = fy - by, wz = fz - bz;
        const float2* __restrict__ tab =
            reinterpret_cast<const float2*>(tables) + (size_t)l * TSIZE;

        float f0 = 0.f, f1 = 0.f;
#pragma unroll
        for (int c = 0; c < 8; c++) {
            const int oi = (c >> 2) & 1, oj = (c >> 1) & 1, ok = c & 1;
            unsigned h = (unsigned)(ix + oi) * 1u
                       ^ (unsigned)(iy + oj) * 2654435761u
                       ^ (unsigned)(iz + ok) * 805459861u;
            h &= (TSIZE - 1);
            const float2 e = __ldg(tab + h);
            const float cw = (oi ? wx : 1.f - wx)
                           * (oj ? wy : 1.f - wy)
                           * (ok ? wz : 1.f - wz);
            f0 = fmaf(e.x, cw, f0);
            f1 = fmaf(e.y, cw, f1);
        }
        feat[2 * l + 0] = f0;
        feat[2 * l + 1] = f1;
    }

#pragma unroll
    for (int c = 0; c < 8; c++)
        g_feat[c * NPTS + i] = make_float4(feat[4 * c + 0], feat[4 * c + 1],
                                           feat[4 * c + 2], feat[4 * c + 3]);
}

// ======================= Kernel B: MLPs + SH + heads =======================
__global__ __launch_bounds__(256, 2) void mlp_kernel(
    const float* __restrict__ dirv,     // [N,3]
    const float* __restrict__ W1, const float* __restrict__ B1,
    const float* __restrict__ W2, const float* __restrict__ B2,
    const float* __restrict__ W3, const float* __restrict__ B3,
    const float* __restrict__ W4, const float* __restrict__ B4,
    const float* __restrict__ W5, const float* __restrict__ B5,
    float* __restrict__ out)            // [3N rgb][N sigma]
{
    __shared__ float s[SMEM_TOTAL];

    for (int t = threadIdx.x; t < 2048; t += 256) s[OFF_W1 + t] = W1[t];
    for (int t = threadIdx.x; t < 64;   t += 256) s[OFF_B1 + t] = B1[t];
    for (int t = threadIdx.x; t < 1024; t += 256) s[OFF_W2 + t] = W2[t];
    for (int t = threadIdx.x; t < 16;   t += 256) s[OFF_B2 + t] = B2[t];
    for (int t = threadIdx.x; t < 2624; t += 256) s[OFF_W3 + t] = W3[t];
    for (int t = threadIdx.x; t < 64;   t += 256) s[OFF_B3 + t] = B3[t];
    for (int t = threadIdx.x; t < 4096; t += 256) s[OFF_W4 + t] = W4[t];
    for (int t = threadIdx.x; t < 64;   t += 256) s[OFF_B4 + t] = B4[t];
    for (int t = threadIdx.x; t < 192;  t += 256) s[OFF_W5 + t] = W5[t];
    for (int t = threadIdx.x; t < 3;    t += 256) s[OFF_B5 + t] = B5[t];
    __syncthreads();

    const int i = blockIdx.x * 256 + threadIdx.x;

    // load features (coalesced, chunk-major)
    float feat[32];
#pragma unroll
    for (int c = 0; c < 8; c++) {
        const float4 f = g_feat[c * NPTS + i];
        feat[4 * c + 0] = f.x; feat[4 * c + 1] = f.y;
        feat[4 * c + 2] = f.z; feat[4 * c + 3] = f.w;
    }

    // ------- density MLP: 32 -> 64 (relu) -> 16, packed f32x2 -------
    u64 den[8];
#pragma unroll
    for (int j = 0; j < 8; j++) PACK2(den[j], s[OFF_B2 + 2 * j], s[OFF_B2 + 2 * j + 1]);

    {
        const ulonglong2* __restrict__ W1v = reinterpret_cast<const ulonglong2*>(s + OFF_W1);
        const ulonglong2* __restrict__ W2v = reinterpret_cast<const ulonglong2*>(s + OFF_W2);
#pragma unroll
        for (int cch = 0; cch < 4; cch++) {         // hidden units [16c,16c+16)
            u64 yc[8];
#pragma unroll
            for (int j = 0; j < 8; j++)
                PACK2(yc[j], s[OFF_B1 + cch * 16 + 2 * j], s[OFF_B1 + cch * 16 + 2 * j + 1]);
#pragma unroll
            for (int k = 0; k < 32; k++) {
                u64 vv; PACK2(vv, feat[k], feat[k]);
#pragma unroll
                for (int j2 = 0; j2 < 4; j2++) {
                    const ulonglong2 w = W1v[k * 16 + cch * 4 + j2];
                    FMA2(yc[2 * j2 + 0], vv, w.x, yc[2 * j2 + 0]);
                    FMA2(yc[2 * j2 + 1], vv, w.y, yc[2 * j2 + 1]);
                }
            }
            // fold relu(yc) into den via W2 rows (each row: 16 floats = 4 ulonglong2)
#pragma unroll
            for (int k2 = 0; k2 < 8; k2++) {
                float a, b; UNPACK2(a, b, yc[k2]);
                a = fmaxf(a, 0.f); b = fmaxf(b, 0.f);
                u64 va; PACK2(va, a, a);
                u64 vb; PACK2(vb, b, b);
                const int kk = cch * 16 + 2 * k2;
#pragma unroll
                for (int j2 = 0; j2 < 4; j2++) {
                    const ulonglong2 wa = W2v[kk * 4 + j2];
                    FMA2(den[2 * j2 + 0], va, wa.x, den[2 * j2 + 0]);
                    FMA2(den[2 * j2 + 1], va, wa.y, den[2 * j2 + 1]);
                }
#pragma unroll
                for (int j2 = 0; j2 < 4; j2++) {
                    const ulonglong2 wb = W2v[(kk + 1) * 4 + j2];
                    FMA2(den[2 * j2 + 0], vb, wb.x, den[2 * j2 + 0]);
                    FMA2(den[2 * j2 + 1], vb, wb.y, den[2 * j2 + 1]);
                }
            }
        }
    }

    float den_s[16];
#pragma unroll
    for (int j = 0; j < 8; j++) UNPACK2(den_s[2 * j], den_s[2 * j + 1], den[j]);
    out[3 * NPTS + i] = fmaxf(den_s[15], 0.f);

    // ---------------- SH degree-4 encoding (25) ----------------
    float sh[25];
    {
        const float x = dirv[3 * i + 0];
        const float yv = dirv[3 * i + 1];
        const float z = dirv[3 * i + 2];
        const float x2 = x * x, y2 = yv * yv, z2 = z * z;
        const float xy = x * yv, xz = x * z, yz = yv * z;
        const float x4 = x2 * x2, y4 = y2 * y2;

        sh[0] = 0.28209479177387814f;
        const float c1 = 0.4886025119029199f;
        sh[1] = -c1 * yv;
        sh[2] =  c1 * z;
        sh[3] = -c1 * x;
        const float sub = 0.31539156525252005f;
        const float v1 = 0.5462742152960396f;
        const float v2 = 1.0925484305920792f;
        const float v3 = 0.9461746957575601f;
        sh[4] =  v2 * xy;
        sh[5] = -v2 * yz;
        sh[6] =  v3 * z2 - sub;
        sh[7] = -v2 * xz;
        sh[8] =  v1 * x2 - v1 * y2;
        const float w1 = 1.445305721320277f;
        const float w2 = 2.890611442640554f;
        const float w3 = 0.5900435899266435f;
        const float w4 = 0.304697199642977f;
        sh[9]  = -w3 * yv * (3.0f * x2 - y2);
        sh[10] =  w2 * xy * z;
        sh[11] =  w4 * yv * (1.5f - 7.5f * z2);
        sh[12] =  1.24392110863372f * z * (1.5f * z2 - 0.5f) - 0.497568443453487f * z;
        sh[13] =  w4 * x * (1.5f - 7.5f * z2);
        sh[14] =  w1 * z * (x2 - y2);
        sh[15] = -w3 * x * (x2 - 3.0f * y2);
        sh[16] =  2.5033429417967f * xy * (x2 - y2);
        sh[17] = -1.77013076977993f * yz * (3.0f * x2 - y2);
        sh[18] =  0.126156626101008f * xy * (52.5f * z2 - 7.5f);
        sh[19] =  0.267618617422916f * yv * (2.33333333333333f * z * (1.5f - 7.5f * z2) + 4.0f * z);
        sh[20] =  1.48099765681286f * z * (1.66666666666667f * z * (1.5f * z2 - 0.5f)
                                           - 0.666666666666667f * z)
                  - 0.952069922236839f * z2 + 0.317356640745613f;
        sh[21] =  0.267618617422916f * x * (2.33333333333333f * z * (1.5f - 7.5f * z2) + 4.0f * z);
        sh[22] =  0.063078313050504f * (x2 - y2) * (52.5f * z2 - 7.5f);
        sh[23] = -1.77013076977993f * xz * (x2 - 3.0f * y2);
        sh[24] = -3.75501441269506f * x2 * y2 + 0.625835735449176f * x4 + 0.625835735449176f * y4;
    }

    // ---------------- color MLP layer 1: 41 -> 64 (relu), packed ----------------
    u64 h1[32];
    {
        const ulonglong2* __restrict__ Wv = reinterpret_cast<const ulonglong2*>(s + OFF_W3);
#pragma unroll
        for (int j = 0; j < 32; j++)
            PACK2(h1[j], s[OFF_B3 + 2 * j], s[OFF_B3 + 2 * j + 1]);
#pragma unroll
        for (int k = 0; k < 41; k++) {
            const float v = (k < 16) ? den_s[k] : sh[k - 16];
            u64 vv; PACK2(vv, v, v);
#pragma unroll
            for (int j2 = 0; j2 < 16; j2++) {
                const ulonglong2 w = Wv[k * 16 + j2];
                FMA2(h1[2 * j2 + 0], vv, w.x, h1[2 * j2 + 0]);
                FMA2(h1[2 * j2 + 1], vv, w.y, h1[2 * j2 + 1]);
            }
        }
    }

    float h1s[64];
#pragma unroll
    for (int j = 0; j < 32; j++) {
        float a, b; UNPACK2(a, b, h1[j]);
        h1s[2 * j]     = fmaxf(a, 0.f);
        h1s[2 * j + 1] = fmaxf(b, 0.f);
    }

    // ------- color MLP layer 2 + head: h2 chunked, packed, folded into rgb -------
    float r0 = s[OFF_B5 + 0], r1 = s[OFF_B5 + 1], r2 = s[OFF_B5 + 2];
    {
        const ulonglong2* __restrict__ W4v = reinterpret_cast<const ulonglong2*>(s + OFF_W4);
#pragma unroll
        for (int cch = 0; cch < 4; cch++) {         // h2 outputs [16c,16c+16)
            u64 hc[8];
#pragma unroll
            for (int j = 0; j < 8; j++)
                PACK2(hc[j], s[OFF_B4 + cch * 16 + 2 * j], s[OFF_B4 + cch * 16 + 2 * j + 1]);
#pragma unroll
            for (int k = 0; k < 64; k++) {
                u64 vv; PACK2(vv, h1s[k], h1s[k]);
#pragma unroll
                for (int j2 = 0; j2 < 4; j2++) {
                    const ulonglong2 w = W4v[k * 16 + cch * 4 + j2];
                    FMA2(hc[2 * j2 + 0], vv, w.x, hc[2 * j2 + 0]);
                    FMA2(hc[2 * j2 + 1], vv, w.y, hc[2 * j2 + 1]);
                }
            }
#pragma unroll
            for (int k2 = 0; k2 < 8; k2++) {
                float a, b; UNPACK2(a, b, hc[k2]);
                a = fmaxf(a, 0.f); b = fmaxf(b, 0.f);
                const int kk = cch * 16 + 2 * k2;
                r0 = fmaf(a, s[OFF_W5 + kk * 3 + 0], r0);
                r1 = fmaf(a, s[OFF_W5 + kk * 3 + 1], r1);
                r2 = fmaf(a, s[OFF_W5 + kk * 3 + 2], r2);
                r0 = fmaf(b, s[OFF_W5 + (kk + 1) * 3 + 0], r0);
                r1 = fmaf(b, s[OFF_W5 + (kk + 1) * 3 + 1], r1);
                r2 = fmaf(b, s[OFF_W5 + (kk + 1) * 3 + 2], r2);
            }
        }
    }

    r0 = 1.0f / (1.0f + __expf(-r0));
    r1 = 1.0f / (1.0f + __expf(-r1));
    r2 = 1.0f / (1.0f + __expf(-r2));

    out[3 * i + 0] = r0;
    out[3 * i + 1] = r1;
    out[3 * i + 2] = r2;
}

extern "C" void kernel_launch(void* const* d_in, const int* in_sizes, int n_in,
                              void* d_out, int out_size)
{
    const float* pos    = (const float*)d_in[0];
    const float* dirv   = (const float*)d_in[1];
    const float* tables = (const float*)d_in[2];
    const float* W1 = (const float*)d_in[3];
    const float* B1 = (const float*)d_in[4];
    const float* W2 = (const float*)d_in[5];
    const float* B2 = (const float*)d_in[6];
    const float* W3 = (const float*)d_in[7];
    const float* B3 = (const float*)d_in[8];
    const float* W4 = (const float*)d_in[9];
    const float* B4 = (const float*)d_in[10];
    const float* W5 = (const float*)d_in[11];
    const float* B5 = (const float*)d_in[12];
    float* out = (float*)d_out;

    encode_kernel<<<NPTS / 256, 256>>>(pos, tables);
    mlp_kernel<<<NPTS / 256, 256>>>(
        dirv, W1, B1, W2, B2, W3, B3, W4, B4, W5, B5, out);
}

// round 7
// speedup vs baseline: 1.0060x; 1.0060x over previous
#include <cuda_runtime.h>
#include <math.h>

#define NPTS   524288
#define NLVL   16
#define TSIZE  (1 << 19)
#define PTS_PER_THREAD 2
#define GRID_BLOCKS (NPTS / 256 / PTS_PER_THREAD)

// shared-memory parameter layout (floats)
#define OFF_W1 0        // [32,64]  2048
#define OFF_B1 2048     // [64]
#define OFF_W2 2112     // [64,16]  1024
#define OFF_B2 3136     // [16]
#define OFF_W3 3152     // [41,64]  2624
#define OFF_B3 5776     // [64]
#define OFF_W4 5840     // [64,64]  4096
#define OFF_B4 9936     // [64]
#define OFF_W5 10000    // [64,3]   192
#define OFF_B5 10192    // [3]
#define SMEM_TOTAL 10196

// packed f32x2 helpers (FFMA2 is only reachable via PTX on sm_103a)
#define FMA2(d, a, b, c) \
    asm("fma.rn.f32x2 %0, %1, %2, %3;" : "=l"(d) : "l"(a), "l"(b), "l"(c))
#define PACK2(d, lo, hi) \
    asm("mov.b64 %0, {%1, %2};" : "=l"(d) : "f"(lo), "f"(hi))
#define UNPACK2(lo, hi, v) \
    asm("mov.b64 {%0, %1}, %2;" : "=f"(lo), "=f"(hi) : "l"(v))

typedef unsigned long long u64;

__global__ __launch_bounds__(256, 2) void nerf_fused_kernel(
    const float* __restrict__ pos,      // [N,3]
    const float* __restrict__ dirv,     // [N,3]
    const float* __restrict__ tables,   // [L,T,F]
    const float* __restrict__ W1, const float* __restrict__ B1,
    const float* __restrict__ W2, const float* __restrict__ B2,
    const float* __restrict__ W3, const float* __restrict__ B3,
    const float* __restrict__ W4, const float* __restrict__ B4,
    const float* __restrict__ W5, const float* __restrict__ B5,
    float* __restrict__ out)            // [3N rgb][N sigma]
{
    __shared__ float s[SMEM_TOTAL];

    for (int t = threadIdx.x; t < 2048; t += 256) s[OFF_W1 + t] = W1[t];
    for (int t = threadIdx.x; t < 64;   t += 256) s[OFF_B1 + t] = B1[t];
    for (int t = threadIdx.x; t < 1024; t += 256) s[OFF_W2 + t] = W2[t];
    for (int t = threadIdx.x; t < 16;   t += 256) s[OFF_B2 + t] = B2[t];
    for (int t = threadIdx.x; t < 2624; t += 256) s[OFF_W3 + t] = W3[t];
    for (int t = threadIdx.x; t < 64;   t += 256) s[OFF_B3 + t] = B3[t];
    for (int t = threadIdx.x; t < 4096; t += 256) s[OFF_W4 + t] = W4[t];
    for (int t = threadIdx.x; t < 64;   t += 256) s[OFF_B4 + t] = B4[t];
    for (int t = threadIdx.x; t < 192;  t += 256) s[OFF_W5 + t] = W5[t];
    for (int t = threadIdx.x; t < 3;    t += 256) s[OFF_B5 + t] = B5[t];
    __syncthreads();

    const int i0 = blockIdx.x * 256 + threadIdx.x;

#pragma unroll 1
    for (int rep = 0; rep < PTS_PER_THREAD; rep++) {
        const int i = i0 + rep * (NPTS / PTS_PER_THREAD);

        // ---------------- hash grid encoding (32 features) ----------------
        const float px = pos[3 * i + 0];
        const float py = pos[3 * i + 1];
        const float pz = pos[3 * i + 2];

        float feat[32];
#pragma unroll
        for (int l = 0; l < NLVL; l++) {
            const float res = (float)(16 << l);      // exact: growth factor b == 2.0
            const float fx = px * res, fy = py * res, fz = pz * res;
            const float bx = floorf(fx), by = floorf(fy), bz = floorf(fz);
            const int ix = (int)bx, iy = (int)by, iz = (int)bz;
            const float wx = fx - bx, wy = fy - by, wz = fz - bz;
            const float2* __restrict__ tab =
                reinterpret_cast<const float2*>(tables) + (size_t)l * TSIZE;

            float f0 = 0.f, f1 = 0.f;
#pragma unroll
            for (int c = 0; c < 8; c++) {
                const int oi = (c >> 2) & 1, oj = (c >> 1) & 1, ok = c & 1;
                unsigned h = (unsigned)(ix + oi) * 1u
                           ^ (unsigned)(iy + oj) * 2654435761u
                           ^ (unsigned)(iz + ok) * 805459861u;
                h &= (TSIZE - 1);
                // fine levels have ~no reuse: stream them (evict-first) to keep
                // L1 for coarse levels / weights
                const float2 e = (l >= 8) ? __ldcs(tab + h) : __ldg(tab + h);
                const float cw = (oi ? wx : 1.f - wx)
                               * (oj ? wy : 1.f - wy)
                               * (ok ? wz : 1.f - wz);
                f0 = fmaf(e.x, cw, f0);
                f1 = fmaf(e.y, cw, f1);
            }
            feat[2 * l + 0] = f0;
            feat[2 * l + 1] = f1;
        }

        // ------- density MLP: 32 -> 64 (relu) -> 16, packed f32x2 -------
        u64 den[8];
#pragma unroll
        for (int j = 0; j < 8; j++) PACK2(den[j], s[OFF_B2 + 2 * j], s[OFF_B2 + 2 * j + 1]);

        {
            const ulonglong2* __restrict__ W1v = reinterpret_cast<const ulonglong2*>(s + OFF_W1);
            const ulonglong2* __restrict__ W2v = reinterpret_cast<const ulonglong2*>(s + OFF_W2);
#pragma unroll
            for (int cch = 0; cch < 4; cch++) {         // hidden units [16c,16c+16)
                u64 yc[8];
#pragma unroll
                for (int j = 0; j < 8; j++)
                    PACK2(yc[j], s[OFF_B1 + cch * 16 + 2 * j], s[OFF_B1 + cch * 16 + 2 * j + 1]);
#pragma unroll
                for (int k = 0; k < 32; k++) {
                    u64 vv; PACK2(vv, feat[k], feat[k]);
#pragma unroll
                    for (int j2 = 0; j2 < 4; j2++) {
                        const ulonglong2 w = W1v[k * 16 + cch * 4 + j2];
                        FMA2(yc[2 * j2 + 0], vv, w.x, yc[2 * j2 + 0]);
                        FMA2(yc[2 * j2 + 1], vv, w.y, yc[2 * j2 + 1]);
                    }
                }
                // fold relu(yc) into den via W2 rows (16 floats = 4 ulonglong2 each)
#pragma unroll
                for (int k2 = 0; k2 < 8; k2++) {
                    float a, b; UNPACK2(a, b, yc[k2]);
                    a = fmaxf(a, 0.f); b = fmaxf(b, 0.f);
                    u64 va; PACK2(va, a, a);
                    u64 vb; PACK2(vb, b, b);
                    const int kk = cch * 16 + 2 * k2;
#pragma unroll
                    for (int j2 = 0; j2 < 4; j2++) {
                        const ulonglong2 wa = W2v[kk * 4 + j2];
                        FMA2(den[2 * j2 + 0], va, wa.x, den[2 * j2 + 0]);
                        FMA2(den[2 * j2 + 1], va, wa.y, den[2 * j2 + 1]);
                    }
#pragma unroll
                    for (int j2 = 0; j2 < 4; j2++) {
                        const ulonglong2 wb = W2v[(kk + 1) * 4 + j2];
                        FMA2(den[2 * j2 + 0], vb, wb.x, den[2 * j2 + 0]);
                        FMA2(den[2 * j2 + 1], vb, wb.y, den[2 * j2 + 1]);
                    }
                }
            }
        }

        float den_s[16];
#pragma unroll
        for (int j = 0; j < 8; j++) UNPACK2(den_s[2 * j], den_s[2 * j + 1], den[j]);
        out[3 * NPTS + i] = fmaxf(den_s[15], 0.f);

        // ---------------- SH degree-4 encoding (25) ----------------
        float sh[25];
        {
            const float x = dirv[3 * i + 0];
            const float yv = dirv[3 * i + 1];
            const float z = dirv[3 * i + 2];
            const float x2 = x * x, y2 = yv * yv, z2 = z * z;
            const float xy = x * yv, xz = x * z, yz = yv * z;
            const float x4 = x2 * x2, y4 = y2 * y2;

            sh[0] = 0.28209479177387814f;
            const float c1 = 0.4886025119029199f;
            sh[1] = -c1 * yv;
            sh[2] =  c1 * z;
            sh[3] = -c1 * x;
            const float sub = 0.31539156525252005f;
            const float v1 = 0.5462742152960396f;
            const float v2 = 1.0925484305920792f;
            const float v3 = 0.9461746957575601f;
            sh[4] =  v2 * xy;
            sh[5] = -v2 * yz;
            sh[6] =  v3 * z2 - sub;
            sh[7] = -v2 * xz;
            sh[8] =  v1 * x2 - v1 * y2;
            const float w1 = 1.445305721320277f;
            const float w2 = 2.890611442640554f;
            const float w3 = 0.5900435899266435f;
            const float w4 = 0.304697199642977f;
            sh[9]  = -w3 * yv * (3.0f * x2 - y2);
            sh[10] =  w2 * xy * z;
            sh[11] =  w4 * yv * (1.5f - 7.5f * z2);
            sh[12] =  1.24392110863372f * z * (1.5f * z2 - 0.5f) - 0.497568443453487f * z;
            sh[13] =  w4 * x * (1.5f - 7.5f * z2);
            sh[14] =  w1 * z * (x2 - y2);
            sh[15] = -w3 * x * (x2 - 3.0f * y2);
            sh[16] =  2.5033429417967f * xy * (x2 - y2);
            sh[17] = -1.77013076977993f * yz * (3.0f * x2 - y2);
            sh[18] =  0.126156626101008f * xy * (52.5f * z2 - 7.5f);
            sh[19] =  0.267618617422916f * yv * (2.33333333333333f * z * (1.5f - 7.5f * z2) + 4.0f * z);
            sh[20] =  1.48099765681286f * z * (1.66666666666667f * z * (1.5f * z2 - 0.5f)
                                               - 0.666666666666667f * z)
                      - 0.952069922236839f * z2 + 0.317356640745613f;
            sh[21] =  0.267618617422916f * x * (2.33333333333333f * z * (1.5f - 7.5f * z2) + 4.0f * z);
            sh[22] =  0.063078313050504f * (x2 - y2) * (52.5f * z2 - 7.5f);
            sh[23] = -1.77013076977993f * xz * (x2 - 3.0f * y2);
            sh[24] = -3.75501441269506f * x2 * y2 + 0.625835735449176f * x4 + 0.625835735449176f * y4;
        }

        // ---------------- color MLP layer 1: 41 -> 64 (relu), packed ----------------
        u64 h1[32];
        {
            const ulonglong2* __restrict__ Wv = reinterpret_cast<const ulonglong2*>(s + OFF_W3);
#pragma unroll
            for (int j = 0; j < 32; j++)
                PACK2(h1[j], s[OFF_B3 + 2 * j], s[OFF_B3 + 2 * j + 1]);
#pragma unroll
            for (int k = 0; k < 41; k++) {
                const float v = (k < 16) ? den_s[k] : sh[k - 16];
                u64 vv; PACK2(vv, v, v);
#pragma unroll
                for (int j2 = 0; j2 < 16; j2++) {
                    const ulonglong2 w = Wv[k * 16 + j2];
                    FMA2(h1[2 * j2 + 0], vv, w.x, h1[2 * j2 + 0]);
                    FMA2(h1[2 * j2 + 1], vv, w.y, h1[2 * j2 + 1]);
                }
            }
        }

        float h1s[64];
#pragma unroll
        for (int j = 0; j < 32; j++) {
            float a, b; UNPACK2(a, b, h1[j]);
            h1s[2 * j]     = fmaxf(a, 0.f);
            h1s[2 * j + 1] = fmaxf(b, 0.f);
        }

        // ------- color MLP layer 2 + head: h2 chunked, packed, folded into rgb -------
        float r0 = s[OFF_B5 + 0], r1 = s[OFF_B5 + 1], r2 = s[OFF_B5 + 2];
        {
            const ulonglong2* __restrict__ W4v = reinterpret_cast<const ulonglong2*>(s + OFF_W4);
#pragma unroll
            for (int cch = 0; cch < 4; cch++) {         // h2 outputs [16c,16c+16)
                u64 hc[8];
#pragma unroll
                for (int j = 0; j < 8; j++)
                    PACK2(hc[j], s[OFF_B4 + cch * 16 + 2 * j], s[OFF_B4 + cch * 16 + 2 * j + 1]);
#pragma unroll
                for (int k = 0; k < 64; k++) {
                    u64 vv; PACK2(vv, h1s[k], h1s[k]);
#pragma unroll
                    for (int j2 = 0; j2 < 4; j2++) {
                        const ulonglong2 w = W4v[k * 16 + cch * 4 + j2];
                        FMA2(hc[2 * j2 + 0], vv, w.x, hc[2 * j2 + 0]);
                        FMA2(hc[2 * j2 + 1], vv, w.y, hc[2 * j2 + 1]);
                    }
                }
#pragma unroll
                for (int k2 = 0; k2 < 8; k2++) {
                    float a, b; UNPACK2(a, b, hc[k2]);
                    a = fmaxf(a, 0.f); b = fmaxf(b, 0.f);
                    const int kk = cch * 16 + 2 * k2;
                    r0 = fmaf(a, s[OFF_W5 + kk * 3 + 0], r0);
                    r1 = fmaf(a, s[OFF_W5 + kk * 3 + 1], r1);
                    r2 = fmaf(a, s[OFF_W5 + kk * 3 + 2], r2);
                    r0 = fmaf(b, s[OFF_W5 + (kk + 1) * 3 + 0], r0);
                    r1 = fmaf(b, s[OFF_W5 + (kk + 1) * 3 + 1], r1);
                    r2 = fmaf(b, s[OFF_W5 + (kk + 1) * 3 + 2], r2);
                }
            }
        }

        r0 = 1.0f / (1.0f + __expf(-r0));
        r1 = 1.0f / (1.0f + __expf(-r1));
        r2 = 1.0f / (1.0f + __expf(-r2));

        out[3 * i + 0] = r0;
        out[3 * i + 1] = r1;
        out[3 * i + 2] = r2;
    }
}

extern "C" void kernel_launch(void* const* d_in, const int* in_sizes, int n_in,
                              void* d_out, int out_size)
{
    const float* pos    = (const float*)d_in[0];
    const float* dirv   = (const float*)d_in[1];
    const float* tables = (const float*)d_in[2];
    const float* W1 = (const float*)d_in[3];
    const float* B1 = (const float*)d_in[4];
    const float* W2 = (const float*)d_in[5];
    const float* B2 = (const float*)d_in[6];
    const float* W3 = (const float*)d_in[7];
    const float* B3 = (const float*)d_in[8];
    const float* W4 = (const float*)d_in[9];
    const float* B4 = (const float*)d_in[10];
    const float* W5 = (const float*)d_in[11];
    const float* B5 = (const float*)d_in[12];
    float* out = (float*)d_out;

    nerf_fused_kernel<<<GRID_BLOCKS, 256>>>(
        pos, dirv, tables,
        W1, B1, W2, B2, W3, B3, W4, B4, W5, B5, out);
}

// round 9
// speedup vs baseline: 1.1665x; 1.1596x over previous
#include <cuda_runtime.h>
#include <cuda_fp16.h>
#include <math.h>

#define NPTS   524288
#define NLVL   16
#define TSIZE  (1 << 19)

// density weights (fp32) shared layout
#define OFF_W1 0        // [32,64]  2048
#define OFF_B1 2048     // [64]
#define OFF_W2 2112     // [64,16]  1024
#define OFF_B2 3136     // [16]
#define DW_TOTAL 3152
// head weights
#define OFF_W5 0        // [64,3] 192
#define OFF_B5 192      // [3]
#define OFF_B4 195      // [64]
#define HW_TOTAL 259

#define A_STRIDE_B  112   // 48 halfs padded to 56 (112B) - conflict-free ldmatrix
#define W3_STRIDE_B 112   // [n][k] rows, K=48 halfs padded
#define W4_STRIDE_B 144   // [n][k] rows, K=64 halfs padded to 72

// packed f32x2 helpers for the fp32 density MLP
#define FMA2(d, a, b, c) \
    asm("fma.rn.f32x2 %0, %1, %2, %3;" : "=l"(d) : "l"(a), "l"(b), "l"(c))
#define PACK2(d, lo, hi) \
    asm("mov.b64 %0, {%1, %2};" : "=l"(d) : "f"(lo), "f"(hi))
#define UNPACK2(lo, hi, v) \
    asm("mov.b64 {%0, %1}, %2;" : "=f"(lo), "=f"(hi) : "l"(v))
typedef unsigned long long u64;

static __device__ __forceinline__ unsigned smem_u32(const void* p) {
    unsigned a;
    asm("{ .reg .u64 t; cvta.to.shared.u64 t, %1; cvt.u32.u64 %0, t; }" : "=r"(a) : "l"(p));
    return a;
}

#define LDMATRIX_X4(r0, r1, r2, r3, addr) \
    asm volatile("ldmatrix.sync.aligned.m8n8.x4.shared.b16 {%0,%1,%2,%3}, [%4];" \
        : "=r"(r0), "=r"(r1), "=r"(r2), "=r"(r3) : "r"(addr))

#define MMA16816(c, a, b0v, b1v) \
    asm volatile("mma.sync.aligned.m16n8k16.row.col.f32.f16.f16.f32 " \
        "{%0,%1,%2,%3}, {%4,%5,%6,%7}, {%8,%9}, {%0,%1,%2,%3};" \
        : "+f"((c)[0]), "+f"((c)[1]), "+f"((c)[2]), "+f"((c)[3]) \
        : "r"((a)[0]), "r"((a)[1]), "r"((a)[2]), "r"((a)[3]), "r"(b0v), "r"(b1v))

__global__ __launch_bounds__(128, 4) void nerf_hmma_kernel(
    const float* __restrict__ pos,
    const float* __restrict__ dirv,
    const float* __restrict__ tables,
    const float* __restrict__ W1, const float* __restrict__ B1,
    const float* __restrict__ W2, const float* __restrict__ B2,
    const float* __restrict__ W3, const float* __restrict__ B3,
    const float* __restrict__ W4, const float* __restrict__ B4,
    const float* __restrict__ W5, const float* __restrict__ B5,
    float* __restrict__ out)
{
    __shared__ __align__(16) unsigned char sA[128 * A_STRIDE_B];    // 14336B A1 staging
    __shared__ __align__(16) unsigned char sW3T[64 * W3_STRIDE_B];  // 7168B  W3^T(+bias col 41) f16
    __shared__ __align__(16) unsigned char sW4T[64 * W4_STRIDE_B];  // 9216B  W4^T f16
    __shared__ float sDW[DW_TOTAL];
    __shared__ float sHW[HW_TOTAL];

    const int tid  = threadIdx.x;
    const int lane = tid & 31;
    const int w    = tid >> 5;
    const int g    = lane >> 2;   // 0..7
    const int t4   = lane & 3;    // 0..3

    // ---- stage density + head weights (fp32) ----
    for (int t = tid; t < 2048; t += 128) sDW[OFF_W1 + t] = W1[t];
    for (int t = tid; t < 64;   t += 128) sDW[OFF_B1 + t] = B1[t];
    for (int t = tid; t < 1024; t += 128) sDW[OFF_W2 + t] = W2[t];
    for (int t = tid; t < 16;   t += 128) sDW[OFF_B2 + t] = B2[t];
    for (int t = tid; t < 192;  t += 128) sHW[OFF_W5 + t] = W5[t];
    for (int t = tid; t < 3;    t += 128) sHW[OFF_B5 + t] = B5[t];
    for (int t = tid; t < 64;   t += 128) sHW[OFF_B4 + t] = B4[t];

    // ---- stage W3^T [n][k] fp16 (K=48: 41 weights, bias at k=41, zeros after) ----
    for (int idx = tid; idx < 64 * 56; idx += 128) {
        const int n = idx / 56, k = idx % 56;
        float v = 0.0f;
        if (k < 41) v = W3[k * 64 + n];
        else if (k == 41) v = B3[n];
        *reinterpret_cast<__half*>(sW3T + n * W3_STRIDE_B + k * 2) = __float2half_rn(v);
    }
    // ---- stage W4^T [n][k] fp16 (K=64, pad to 72) ----
    for (int idx = tid; idx < 64 * 72; idx += 128) {
        const int n = idx / 72, k = idx % 72;
        const float v = (k < 64) ? W4[k * 64 + n] : 0.0f;
        *reinterpret_cast<__half*>(sW4T + n * W4_STRIDE_B + k * 2) = __float2half_rn(v);
    }
    __syncthreads();

    const int i = blockIdx.x * 128 + tid;

    // ---------------- hash grid encoding (32 features) ----------------
    const float px = pos[3 * i + 0];
    const float py = pos[3 * i + 1];
    const float pz = pos[3 * i + 2];

    float feat[32];
#pragma unroll
    for (int l = 0; l < NLVL; l++) {
        const float res = (float)(16 << l);
        const float fx = px * res, fy = py * res, fz = pz * res;
        const float bx = floorf(fx), by = floorf(fy), bz = floorf(fz);
        const int ix = (int)bx, iy = (int)by, iz = (int)bz;
        const float wx = fx - bx, wy = fy - by, wz = fz - bz;
        const float2* __restrict__ tab =
            reinterpret_cast<const float2*>(tables) + (size_t)l * TSIZE;
        float f0 = 0.f, f1 = 0.f;
#pragma unroll
        for (int c = 0; c < 8; c++) {
            const int oi = (c >> 2) & 1, oj = (c >> 1) & 1, ok = c & 1;
            unsigned h = (unsigned)(ix + oi) * 1u
                       ^ (unsigned)(iy + oj) * 2654435761u
                       ^ (unsigned)(iz + ok) * 805459861u;
            h &= (TSIZE - 1);
            const float2 e = __ldg(tab + h);
            const float cw = (oi ? wx : 1.f - wx) * (oj ? wy : 1.f - wy) * (ok ? wz : 1.f - wz);
            f0 = fmaf(e.x, cw, f0);
            f1 = fmaf(e.y, cw, f1);
        }
        feat[2 * l + 0] = f0;
        feat[2 * l + 1] = f1;
    }

    // ------- density MLP (fp32, packed f32x2): 32 -> 64 relu -> 16 -------
    u64 den[8];
#pragma unroll
    for (int j = 0; j < 8; j++) PACK2(den[j], sDW[OFF_B2 + 2 * j], sDW[OFF_B2 + 2 * j + 1]);
    {
        const ulonglong2* __restrict__ W1v = reinterpret_cast<const ulonglong2*>(sDW + OFF_W1);
        const ulonglong2* __restrict__ W2v = reinterpret_cast<const ulonglong2*>(sDW + OFF_W2);
#pragma unroll
        for (int cch = 0; cch < 4; cch++) {
            u64 yc[8];
#pragma unroll
            for (int j = 0; j < 8; j++)
                PACK2(yc[j], sDW[OFF_B1 + cch * 16 + 2 * j], sDW[OFF_B1 + cch * 16 + 2 * j + 1]);
#pragma unroll
            for (int k = 0; k < 32; k++) {
                u64 vv; PACK2(vv, feat[k], feat[k]);
#pragma unroll
                for (int j2 = 0; j2 < 4; j2++) {
                    const ulonglong2 wv = W1v[k * 16 + cch * 4 + j2];
                    FMA2(yc[2 * j2 + 0], vv, wv.x, yc[2 * j2 + 0]);
                    FMA2(yc[2 * j2 + 1], vv, wv.y, yc[2 * j2 + 1]);
                }
            }
#pragma unroll
            for (int k2 = 0; k2 < 8; k2++) {
                float a, b; UNPACK2(a, b, yc[k2]);
                a = fmaxf(a, 0.f); b = fmaxf(b, 0.f);
                u64 va; PACK2(va, a, a);
                u64 vb; PACK2(vb, b, b);
                const int kk = cch * 16 + 2 * k2;
#pragma unroll
                for (int j2 = 0; j2 < 4; j2++) {
                    const ulonglong2 wa = W2v[kk * 4 + j2];
                    FMA2(den[2 * j2 + 0], va, wa.x, den[2 * j2 + 0]);
                    FMA2(den[2 * j2 + 1], va, wa.y, den[2 * j2 + 1]);
                }
#pragma unroll
                for (int j2 = 0; j2 < 4; j2++) {
                    const ulonglong2 wb = W2v[(kk + 1) * 4 + j2];
                    FMA2(den[2 * j2 + 0], vb, wb.x, den[2 * j2 + 0]);
                    FMA2(den[2 * j2 + 1], vb, wb.y, den[2 * j2 + 1]);
                }
            }
        }
    }
    float den_s[16];
#pragma unroll
    for (int j = 0; j < 8; j++) UNPACK2(den_s[2 * j], den_s[2 * j + 1], den[j]);
    out[3 * NPTS + i] = fmaxf(den_s[15], 0.f);   // sigma: exact fp32

    // ---------------- SH degree-4 (25) ----------------
    float sh[25];
    {
        const float x = dirv[3 * i + 0];
        const float yv = dirv[3 * i + 1];
        const float z = dirv[3 * i + 2];
        const float x2 = x * x, y2 = yv * yv, z2 = z * z;
        const float xy = x * yv, xz = x * z, yz = yv * z;
        const float x4 = x2 * x2, y4 = y2 * y2;
        sh[0] = 0.28209479177387814f;
        const float c1 = 0.4886025119029199f;
        sh[1] = -c1 * yv; sh[2] = c1 * z; sh[3] = -c1 * x;
        const float sub = 0.31539156525252005f;
        const float v1 = 0.5462742152960396f, v2 = 1.0925484305920792f, v3 = 0.9461746957575601f;
        sh[4] = v2 * xy; sh[5] = -v2 * yz; sh[6] = v3 * z2 - sub; sh[7] = -v2 * xz;
        sh[8] = v1 * x2 - v1 * y2;
        const float w1c = 1.445305721320277f, w2c = 2.890611442640554f;
        const float w3c = 0.5900435899266435f, w4c = 0.304697199642977f;
        sh[9]  = -w3c * yv * (3.0f * x2 - y2);
        sh[10] =  w2c * xy * z;
        sh[11] =  w4c * yv * (1.5f - 7.5f * z2);
        sh[12] =  1.24392110863372f * z * (1.5f * z2 - 0.5f) - 0.497568443453487f * z;
        sh[13] =  w4c * x * (1.5f - 7.5f * z2);
        sh[14] =  w1c * z * (x2 - y2);
        sh[15] = -w3c * x * (x2 - 3.0f * y2);
        sh[16] =  2.5033429417967f * xy * (x2 - y2);
        sh[17] = -1.77013076977993f * yz * (3.0f * x2 - y2);
        sh[18] =  0.126156626101008f * xy * (52.5f * z2 - 7.5f);
        sh[19] =  0.267618617422916f * yv * (2.33333333333333f * z * (1.5f - 7.5f * z2) + 4.0f * z);
        sh[20] =  1.48099765681286f * z * (1.66666666666667f * z * (1.5f * z2 - 0.5f)
                                           - 0.666666666666667f * z)
                  - 0.952069922236839f * z2 + 0.317356640745613f;
        sh[21] =  0.267618617422916f * x * (2.33333333333333f * z * (1.5f - 7.5f * z2) + 4.0f * z);
        sh[22] =  0.063078313050504f * (x2 - y2) * (52.5f * z2 - 7.5f);
        sh[23] = -1.77013076977993f * xz * (x2 - 3.0f * y2);
        sh[24] = -3.75501441269506f * x2 * y2 + 0.625835735449176f * x4 + 0.625835735449176f * y4;
    }

    // ---- stage A1 row (48 f16: den16 | sh25 | 1.0 | zeros) ----
    {
        __half v[48];
#pragma unroll
        for (int k = 0; k < 16; k++) v[k] = __float2half_rn(den_s[k]);
#pragma unroll
        for (int k = 0; k < 25; k++) v[16 + k] = __float2half_rn(sh[k]);
        v[41] = __float2half_rn(1.0f);
#pragma unroll
        for (int k = 42; k < 48; k++) v[k] = __float2half_rn(0.0f);
        const uint4* vv = reinterpret_cast<const uint4*>(v);
        unsigned char* row = sA + tid * A_STRIDE_B;
#pragma unroll
        for (int q = 0; q < 6; q++)
            *reinterpret_cast<uint4*>(row + q * 16) = vv[q];
    }
    __syncwarp();

    // ---- load A1 fragments via ldmatrix (2 m-tiles x 3 k-tiles) ----
    unsigned a1f[2][3][4];
    {
        const unsigned base = smem_u32(sA);
        const int m = lane >> 3, r = lane & 7;
#pragma unroll
        for (int mt = 0; mt < 2; mt++) {
#pragma unroll
            for (int kk = 0; kk < 3; kk++) {
                const int row = w * 32 + mt * 16 + (m & 1) * 8 + r;
                const unsigned addr = base + row * A_STRIDE_B + kk * 32 + (m >> 1) * 16;
                LDMATRIX_X4(a1f[mt][kk][0], a1f[mt][kk][1], a1f[mt][kk][2], a1f[mt][kk][3], addr);
            }
        }
    }

    // ---- layer 1 MMA: h1_pre[32pts x 64] ----
    float acc1[2][8][4];
#pragma unroll
    for (int mt = 0; mt < 2; mt++)
#pragma unroll
        for (int nt = 0; nt < 8; nt++)
#pragma unroll
            for (int c = 0; c < 4; c++) acc1[mt][nt][c] = 0.f;
    {
        const unsigned char* bbase = sW3T + (g * W3_STRIDE_B) + 4 * t4;
#pragma unroll
        for (int nt = 0; nt < 8; nt++) {
#pragma unroll
            for (int kk = 0; kk < 3; kk++) {
                const unsigned char* p = bbase + nt * 8 * W3_STRIDE_B + kk * 32;
                const unsigned b0v = *reinterpret_cast<const unsigned*>(p);
                const unsigned b1v = *reinterpret_cast<const unsigned*>(p + 16);
                MMA16816(acc1[0][nt], a1f[0][kk], b0v, b1v);
                MMA16816(acc1[1][nt], a1f[1][kk], b0v, b1v);
            }
        }
    }

    // ---- relu + repack to A2 fragments (register-only) ----
    unsigned a2f[2][4][4];
#pragma unroll
    for (int mt = 0; mt < 2; mt++) {
#pragma unroll
        for (int kk = 0; kk < 4; kk++) {
            const float* cA = acc1[mt][2 * kk];
            const float* cB = acc1[mt][2 * kk + 1];
            __half2 h0 = __floats2half2_rn(fmaxf(cA[0], 0.f), fmaxf(cA[1], 0.f));
            __half2 h1 = __floats2half2_rn(fmaxf(cA[2], 0.f), fmaxf(cA[3], 0.f));
            __half2 h2 = __floats2half2_rn(fmaxf(cB[0], 0.f), fmaxf(cB[1], 0.f));
            __half2 h3 = __floats2half2_rn(fmaxf(cB[2], 0.f), fmaxf(cB[3], 0.f));
            a2f[mt][kk][0] = *reinterpret_cast<unsigned*>(&h0);
            a2f[mt][kk][1] = *reinterpret_cast<unsigned*>(&h1);
            a2f[mt][kk][2] = *reinterpret_cast<unsigned*>(&h2);
            a2f[mt][kk][3] = *reinterpret_cast<unsigned*>(&h3);
        }
    }

    // ---- layer 2 MMA: h2_pre[32pts x 64] ----
    float acc2[2][8][4];
#pragma unroll
    for (int mt = 0; mt < 2; mt++)
#pragma unroll
        for (int nt = 0; nt < 8; nt++)
#pragma unroll
            for (int c = 0; c < 4; c++) acc2[mt][nt][c] = 0.f;
    {
        const unsigned char* bbase = sW4T + (g * W4_STRIDE_B) + 4 * t4;
#pragma unroll
        for (int nt = 0; nt < 8; nt++) {
#pragma unroll
            for (int kk = 0; kk < 4; kk++) {
                const unsigned char* p = bbase + nt * 8 * W4_STRIDE_B + kk * 32;
                const unsigned b0v = *reinterpret_cast<const unsigned*>(p);
                const unsigned b1v = *reinterpret_cast<const unsigned*>(p + 16);
                MMA16816(acc2[0][nt], a2f[0][kk], b0v, b1v);
                MMA16816(acc2[1][nt], a2f[1][kk], b0v, b1v);
            }
        }
    }

    // ---- head: +b4, relu, 64->3, lane-group reduce, sigmoid ----
    {
        float pr[4][3];
#pragma unroll
        for (int q = 0; q < 4; q++) { pr[q][0] = 0.f; pr[q][1] = 0.f; pr[q][2] = 0.f; }
#pragma unroll
        for (int nt = 0; nt < 8; nt++) {
#pragma unroll
            for (int j = 0; j < 2; j++) {
                const int col = nt * 8 + 2 * t4 + j;
                const float b4v = sHW[OFF_B4 + col];
                const float w50 = sHW[OFF_W5 + col * 3 + 0];
                const float w51 = sHW[OFF_W5 + col * 3 + 1];
                const float w52 = sHW[OFF_W5 + col * 3 + 2];
#pragma unroll
                for (int mt = 0; mt < 2; mt++) {
#pragma unroll
                    for (int hh = 0; hh < 2; hh++) {
                        const float hv = fmaxf(acc2[mt][nt][2 * hh + j] + b4v, 0.f);
                        pr[mt * 2 + hh][0] = fmaf(hv, w50, pr[mt * 2 + hh][0]);
                        pr[mt * 2 + hh][1] = fmaf(hv, w51, pr[mt * 2 + hh][1]);
                        pr[mt * 2 + hh][2] = fmaf(hv, w52, pr[mt * 2 + hh][2]);
                    }
                }
            }
        }
        // reduce across the 4 lanes of each group (same g, t4=0..3)
#pragma unroll
        for (int q = 0; q < 4; q++) {
#pragma unroll
            for (int c = 0; c < 3; c++) {
                float v = pr[q][c];
                v += __shfl_xor_sync(0xffffffffu, v, 1);
                v += __shfl_xor_sync(0xffffffffu, v, 2);
                pr[q][c] = v;
            }
        }
        if (t4 == 0) {
            const float b50 = sHW[OFF_B5 + 0], b51 = sHW[OFF_B5 + 1], b52 = sHW[OFF_B5 + 2];
#pragma unroll
            for (int mt = 0; mt < 2; mt++) {
#pragma unroll
                for (int hh = 0; hh < 2; hh++) {
                    const int p = blockIdx.x * 128 + w * 32 + mt * 16 + hh * 8 + g;
                    const int q = mt * 2 + hh;
                    out[3 * p + 0] = 1.0f / (1.0f + __expf(-(pr[q][0] + b50)));
                    out[3 * p + 1] = 1.0f / (1.0f + __expf(-(pr[q][1] + b51)));
                    out[3 * p + 2] = 1.0f / (1.0f + __expf(-(pr[q][2] + b52)));
                }
            }
        }
    }
}

extern "C" void kernel_launch(void* const* d_in, const int* in_sizes, int n_in,
                              void* d_out, int out_size)
{
    const float* pos    = (const float*)d_in[0];
    const float* dirv   = (const float*)d_in[1];
    const float* tables = (const float*)d_in[2];
    const float* W1 = (const float*)d_in[3];
    const float* B1 = (const float*)d_in[4];
    const float* W2 = (const float*)d_in[5];
    const float* B2 = (const float*)d_in[6];
    const float* W3 = (const float*)d_in[7];
    const float* B3 = (const float*)d_in[8];
    const float* W4 = (const float*)d_in[9];
    const float* B4 = (const float*)d_in[10];
    const float* W5 = (const float*)d_in[11];
    const float* B5 = (const float*)d_in[12];
    float* out = (float*)d_out;

    nerf_hmma_kernel<<<NPTS / 128, 128>>>(
        pos, dirv, tables,
        W1, B1, W2, B2, W3, B3, W4, B4, W5, B5, out);
}